// round 6
// baseline (speedup 1.0000x reference)
#include <cuda_runtime.h>

// 2D Haar DWT, (16,64,256,256) fp32 -> 4 x (16,64,128,128).
// Collapses the reference's dense DWT matrices into the 2x2 Haar butterfly:
//   LL=0.5(a+b+c+d) LH=0.5(a-b+c-d) HL=0.5(a+b-c-d) HH=0.5(a-b-c+d)
// (0.7071067811865476^2 == 0.5f exactly in fp32.)
// Pure streaming kernel: 256 MB read + 256 MB write, HBM-bound.
// .cs cache hints on both directions: no byte is ever touched twice.

static constexpr int NIMG = 16 * 64;        // 1024 images
static constexpr int H    = 256;
static constexpr int W    = 256;
static constexpr int LH_  = H / 2;          // 128
static constexpr int LW_  = W / 2;          // 128
static constexpr long long BAND = (long long)NIMG * LH_ * LW_;  // 16,777,216 per band

// Each thread: one image n, one output row r, one group of 4 output cols.
// Loads 2 float4 from input row 2r and 2 float4 from row 2r+1 (8 input cols),
// produces one float4 per band.
__global__ void __launch_bounds__(256) dwt2d_haar_kernel(
    const float* __restrict__ x, float* __restrict__ out)
{
    int t = blockIdx.x * blockDim.x + threadIdx.x;
    // t layout: [n:10][r:7][v:5]  (1024 * 128 * 32 = 4,194,304 threads)
    int v = t & 31;          // 0..31  -> out cols 4v..4v+3, in cols 8v..8v+7
    int r = (t >> 5) & 127;  // output row
    int n = t >> 12;         // image index

    const float* base = x + (long long)n * (H * W) + (long long)(2 * r) * W + 8 * v;
    const float4* row0 = reinterpret_cast<const float4*>(base);
    const float4* row1 = reinterpret_cast<const float4*>(base + W);

    // Front-batch 4 independent 16B streaming loads (MLP=4)
    float4 a0 = __ldcs(&row0[0]);
    float4 a1 = __ldcs(&row0[1]);
    float4 b0 = __ldcs(&row1[0]);
    float4 b1 = __ldcs(&row1[1]);

    float4 ll, lh, hl, hh;

    {   // pair 0: a0.xy / b0.xy
        float st = a0.x + a0.y, dt = a0.x - a0.y;
        float sb = b0.x + b0.y, db = b0.x - b0.y;
        ll.x = 0.5f * (st + sb); lh.x = 0.5f * (dt + db);
        hl.x = 0.5f * (st - sb); hh.x = 0.5f * (dt - db);
    }
    {   // pair 1: a0.zw / b0.zw
        float st = a0.z + a0.w, dt = a0.z - a0.w;
        float sb = b0.z + b0.w, db = b0.z - b0.w;
        ll.y = 0.5f * (st + sb); lh.y = 0.5f * (dt + db);
        hl.y = 0.5f * (st - sb); hh.y = 0.5f * (dt - db);
    }
    {   // pair 2: a1.xy / b1.xy
        float st = a1.x + a1.y, dt = a1.x - a1.y;
        float sb = b1.x + b1.y, db = b1.x - b1.y;
        ll.z = 0.5f * (st + sb); lh.z = 0.5f * (dt + db);
        hl.z = 0.5f * (st - sb); hh.z = 0.5f * (dt - db);
    }
    {   // pair 3: a1.zw / b1.zw
        float st = a1.z + a1.w, dt = a1.z - a1.w;
        float sb = b1.z + b1.w, db = b1.z - b1.w;
        ll.w = 0.5f * (st + sb); lh.w = 0.5f * (dt + db);
        hl.w = 0.5f * (st - sb); hh.w = 0.5f * (dt - db);
    }

    long long o = (long long)n * (LH_ * LW_) + (long long)r * LW_ + 4 * v;
    // bands are concatenated: LL, LH, HL, HH — streaming stores (no reuse)
    __stcs(reinterpret_cast<float4*>(out + o),            ll);
    __stcs(reinterpret_cast<float4*>(out + o + BAND),     lh);
    __stcs(reinterpret_cast<float4*>(out + o + 2 * BAND), hl);
    __stcs(reinterpret_cast<float4*>(out + o + 3 * BAND), hh);
}

extern "C" void kernel_launch(void* const* d_in, const int* in_sizes, int n_in,
                              void* d_out, int out_size)
{
    const float* x = (const float*)d_in[0];   // (16,64,256,256) fp32
    float* out = (float*)d_out;               // 4 bands concatenated

    const int total = NIMG * LH_ * 32;        // 4,194,304 threads
    const int threads = 256;
    const int blocks = total / threads;       // 16384
    dwt2d_haar_kernel<<<blocks, threads>>>(x, out);
}

// round 11
// speedup vs baseline: 1.0070x; 1.0070x over previous
#include <cuda_runtime.h>

// 2D Haar DWT, (16,64,256,256) fp32 -> 4 x (16,64,128,128).
// Butterfly form of the reference's dense DWT matrices:
//   LL=0.5(a+b+c+d) LH=0.5(a-b+c-d) HL=0.5(a+b-c-d) HH=0.5(a-b-c+d)
// HBM-bound streaming kernel: 256 MB read + 256 MB write.
// R6: 2 output rows per thread -> 8 front-batched LDG.128 (MLP_p1=8),
// halved thread count, .cs hints both directions (zero reuse).

static constexpr int NIMG = 16 * 64;        // 1024 images
static constexpr int H    = 256;
static constexpr int W    = 256;
static constexpr int LH_  = H / 2;          // 128
static constexpr int LW_  = W / 2;          // 128
static constexpr long long BAND = (long long)NIMG * LH_ * LW_;  // 16,777,216 per band

// One 2x2 butterfly pair from (top-left, top-right, bot-left, bot-right)
__device__ __forceinline__ void bfly(float a, float b, float c, float d,
                                     float& ll, float& lh, float& hl, float& hh)
{
    float st = a + b, dt = a - b;
    float sb = c + d, db = c - d;
    ll = 0.5f * (st + sb); lh = 0.5f * (dt + db);
    hl = 0.5f * (st - sb); hh = 0.5f * (dt - db);
}

// Compute one float4 per band from two input float4s (top row, bottom row)
__device__ __forceinline__ void quad(float4 t0, float4 t1, float4 b0, float4 b1,
                                     float4& ll, float4& lh, float4& hl, float4& hh)
{
    bfly(t0.x, t0.y, b0.x, b0.y, ll.x, lh.x, hl.x, hh.x);
    bfly(t0.z, t0.w, b0.z, b0.w, ll.y, lh.y, hl.y, hh.y);
    bfly(t1.x, t1.y, b1.x, b1.y, ll.z, lh.z, hl.z, hh.z);
    bfly(t1.z, t1.w, b1.z, b1.w, ll.w, lh.w, hl.w, hh.w);
}

// Each thread: one image n, one PAIR of output rows (2q, 2q+1), 4 output cols.
// Reads input rows 4q..4q+3, cols 8v..8v+7: 8 x LDG.128 front-batched.
__global__ void __launch_bounds__(256) dwt2d_haar_kernel(
    const float* __restrict__ x, float* __restrict__ out)
{
    int t = blockIdx.x * blockDim.x + threadIdx.x;
    // t layout: [n:10][q:6][v:5]  (1024 * 64 * 32 = 2,097,152 threads)
    int v = t & 31;          // out cols 4v..4v+3, in cols 8v..8v+7
    int q = (t >> 5) & 63;   // output row pair: rows 2q, 2q+1
    int n = t >> 11;         // image index

    const float* base = x + (long long)n * (H * W) + (long long)(4 * q) * W + 8 * v;
    const float4* r0 = reinterpret_cast<const float4*>(base);          // in row 4q
    const float4* r1 = reinterpret_cast<const float4*>(base + W);      // in row 4q+1
    const float4* r2 = reinterpret_cast<const float4*>(base + 2 * W);  // in row 4q+2
    const float4* r3 = reinterpret_cast<const float4*>(base + 3 * W);  // in row 4q+3

    // 8 independent 16B streaming loads, front-batched (MLP=8)
    float4 a0 = __ldcs(&r0[0]);
    float4 a1 = __ldcs(&r0[1]);
    float4 b0 = __ldcs(&r1[0]);
    float4 b1 = __ldcs(&r1[1]);
    float4 c0 = __ldcs(&r2[0]);
    float4 c1 = __ldcs(&r2[1]);
    float4 d0 = __ldcs(&r3[0]);
    float4 d1 = __ldcs(&r3[1]);

    float4 ll0, lh0, hl0, hh0, ll1, lh1, hl1, hh1;
    quad(a0, a1, b0, b1, ll0, lh0, hl0, hh0);   // output row 2q
    quad(c0, c1, d0, d1, ll1, lh1, hl1, hh1);   // output row 2q+1

    long long o = (long long)n * (LH_ * LW_) + (long long)(2 * q) * LW_ + 4 * v;
    // bands concatenated: LL, LH, HL, HH — streaming stores
    __stcs(reinterpret_cast<float4*>(out + o),                   ll0);
    __stcs(reinterpret_cast<float4*>(out + o + LW_),             ll1);
    __stcs(reinterpret_cast<float4*>(out + o + BAND),            lh0);
    __stcs(reinterpret_cast<float4*>(out + o + BAND + LW_),      lh1);
    __stcs(reinterpret_cast<float4*>(out + o + 2 * BAND),        hl0);
    __stcs(reinterpret_cast<float4*>(out + o + 2 * BAND + LW_),  hl1);
    __stcs(reinterpret_cast<float4*>(out + o + 3 * BAND),        hh0);
    __stcs(reinterpret_cast<float4*>(out + o + 3 * BAND + LW_),  hh1);
}

extern "C" void kernel_launch(void* const* d_in, const int* in_sizes, int n_in,
                              void* d_out, int out_size)
{
    const float* x = (const float*)d_in[0];   // (16,64,256,256) fp32
    float* out = (float*)d_out;               // 4 bands concatenated

    const int total = NIMG * (LH_ / 2) * 32;  // 2,097,152 threads
    const int threads = 256;
    const int blocks = total / threads;       // 8192
    dwt2d_haar_kernel<<<blocks, threads>>>(x, out);
}

// round 12
// speedup vs baseline: 1.0078x; 1.0008x over previous
#include <cuda_runtime.h>

// 2D Haar DWT, (16,64,256,256) fp32 -> 4 x (16,64,128,128).
// Butterfly form of the reference's dense DWT matrices:
//   LL=0.5(a+b+c+d) LH=0.5(a-b+c-d) HL=0.5(a+b-c-d) HH=0.5(a-b-c+d)
// HBM-bound streaming kernel: 256 MB read + 256 MB write.
// R11 post-mortem: 2-rows/thread (MLP=8) cost occupancy (40 regs, 59%) and
// LOST DRAM% (81.8->79.3). Reverted to 1-row/thread (32 regs, occ 76%,
// DRAM 81.8%) — occupancy-carried MLP is the winning config. 512-thr blocks
// to halve CTA count; .cs hints both directions (zero reuse).

static constexpr int NIMG = 16 * 64;        // 1024 images
static constexpr int H    = 256;
static constexpr int W    = 256;
static constexpr int LH_  = H / 2;          // 128
static constexpr int LW_  = W / 2;          // 128
static constexpr long long BAND = (long long)NIMG * LH_ * LW_;  // 16,777,216 per band

// Each thread: one image n, one output row r, one group of 4 output cols.
// Loads 2 float4 from input row 2r and 2 float4 from row 2r+1 (8 input cols),
// produces one float4 per band. Warp covers a full 256-col input row pair.
__global__ void __launch_bounds__(512) dwt2d_haar_kernel(
    const float* __restrict__ x, float* __restrict__ out)
{
    int t = blockIdx.x * blockDim.x + threadIdx.x;
    // t layout: [n:10][r:7][v:5]  (1024 * 128 * 32 = 4,194,304 threads)
    int v = t & 31;          // 0..31  -> out cols 4v..4v+3, in cols 8v..8v+7
    int r = (t >> 5) & 127;  // output row
    int n = t >> 12;         // image index

    const float* base = x + (long long)n * (H * W) + (long long)(2 * r) * W + 8 * v;
    const float4* row0 = reinterpret_cast<const float4*>(base);
    const float4* row1 = reinterpret_cast<const float4*>(base + W);

    // Front-batch 4 independent 16B streaming loads (MLP=4, occupancy-carried)
    float4 a0 = __ldcs(&row0[0]);
    float4 a1 = __ldcs(&row0[1]);
    float4 b0 = __ldcs(&row1[0]);
    float4 b1 = __ldcs(&row1[1]);

    float4 ll, lh, hl, hh;

    {   // pair 0: a0.xy / b0.xy
        float st = a0.x + a0.y, dt = a0.x - a0.y;
        float sb = b0.x + b0.y, db = b0.x - b0.y;
        ll.x = 0.5f * (st + sb); lh.x = 0.5f * (dt + db);
        hl.x = 0.5f * (st - sb); hh.x = 0.5f * (dt - db);
    }
    {   // pair 1: a0.zw / b0.zw
        float st = a0.z + a0.w, dt = a0.z - a0.w;
        float sb = b0.z + b0.w, db = b0.z - b0.w;
        ll.y = 0.5f * (st + sb); lh.y = 0.5f * (dt + db);
        hl.y = 0.5f * (st - sb); hh.y = 0.5f * (dt - db);
    }
    {   // pair 2: a1.xy / b1.xy
        float st = a1.x + a1.y, dt = a1.x - a1.y;
        float sb = b1.x + b1.y, db = b1.x - b1.y;
        ll.z = 0.5f * (st + sb); lh.z = 0.5f * (dt + db);
        hl.z = 0.5f * (st - sb); hh.z = 0.5f * (dt - db);
    }
    {   // pair 3: a1.zw / b1.zw
        float st = a1.z + a1.w, dt = a1.z - a1.w;
        float sb = b1.z + b1.w, db = b1.z - b1.w;
        ll.w = 0.5f * (st + sb); lh.w = 0.5f * (dt + db);
        hl.w = 0.5f * (st - sb); hh.w = 0.5f * (dt - db);
    }

    long long o = (long long)n * (LH_ * LW_) + (long long)r * LW_ + 4 * v;
    // bands concatenated: LL, LH, HL, HH — streaming stores (no reuse)
    __stcs(reinterpret_cast<float4*>(out + o),            ll);
    __stcs(reinterpret_cast<float4*>(out + o + BAND),     lh);
    __stcs(reinterpret_cast<float4*>(out + o + 2 * BAND), hl);
    __stcs(reinterpret_cast<float4*>(out + o + 3 * BAND), hh);
}

extern "C" void kernel_launch(void* const* d_in, const int* in_sizes, int n_in,
                              void* d_out, int out_size)
{
    const float* x = (const float*)d_in[0];   // (16,64,256,256) fp32
    float* out = (float*)d_out;               // 4 bands concatenated

    const int total = NIMG * LH_ * 32;        // 4,194,304 threads
    const int threads = 512;
    const int blocks = total / threads;       // 8192
    dwt2d_haar_kernel<<<blocks, threads>>>(x, out);
}